// round 15
// baseline (speedup 1.0000x reference)
#include <cuda_runtime.h>
#include <cuda_fp16.h>
#include <math.h>
#include <stdint.h>

// ---------------------------------------------------------------------------
// Shapes
// ---------------------------------------------------------------------------
#define BB     32
#define TT     64
#define NN     128
#define F_IN   16
#define SOUT   16
#define DD     2048
#define NHEADS 16
#define DH     128
#define DFF    2048
#define LAYERS 2
#define NOUT   10
#define ROWS   (BB*TT)
#define DSZ    (ROWS*DD)        // 4M elements; one 2048x2048 matrix

// ---------------------------------------------------------------------------
// Static scratch (allocation-free rule)
// ---------------------------------------------------------------------------
__device__ float g_scratch[7ull * DSZ];                 // h,(qkv fp16),-,-,-,tmp
__device__ unsigned char g_mask[NN * NN];
__device__ __half g_wt[12ull * DSZ];                    // transposed weights fp16
__device__ __half g_a[DSZ];                             // activation fp16 (A)
__device__ __half g_b[DSZ];                             // activation fp16 (B, FFN mid)

// ---------------------------------------------------------------------------
// Helpers
// ---------------------------------------------------------------------------
__device__ __forceinline__ uint32_t smem_u32(const void* p) {
    uint32_t a;
    asm("{ .reg .u64 t; cvta.to.shared.u64 t, %1; cvt.u32.u64 %0, t; }" : "=r"(a) : "l"(p));
    return a;
}

#define CP_ASYNC16(saddr, gptr) \
    asm volatile("cp.async.cg.shared.global [%0], [%1], 16;" :: "r"(saddr), "l"(gptr) : "memory")
#define CP_COMMIT()  asm volatile("cp.async.commit_group;" ::: "memory")
#define CP_WAIT0()   asm volatile("cp.async.wait_group 0;" ::: "memory")

__device__ __forceinline__ void ldsm_x4(uint32_t* r, uint32_t addr) {
    asm volatile("ldmatrix.sync.aligned.m8n8.x4.shared.b16 {%0,%1,%2,%3}, [%4];"
                 : "=r"(r[0]), "=r"(r[1]), "=r"(r[2]), "=r"(r[3]) : "r"(addr));
}
__device__ __forceinline__ void mma_fp16(float* d, const uint32_t* a, const uint32_t* b) {
    asm volatile(
        "mma.sync.aligned.m16n8k16.row.col.f32.f16.f16.f32 "
        "{%0,%1,%2,%3}, {%4,%5,%6,%7}, {%8,%9}, {%0,%1,%2,%3};"
        : "+f"(d[0]), "+f"(d[1]), "+f"(d[2]), "+f"(d[3])
        : "r"(a[0]), "r"(a[1]), "r"(a[2]), "r"(a[3]), "r"(b[0]), "r"(b[1]));
}

// ---------------------------------------------------------------------------
// Mask kernel
// ---------------------------------------------------------------------------
__global__ void mask_kernel(const float* __restrict__ V, const int* __restrict__ cls,
                            unsigned char* __restrict__ mask)
{
    int i = blockIdx.x, j = threadIdx.x;
    int c = *cls;
    float v = V[(size_t)c * NN * NN + i * NN + j];
    float a = (1.0f / (1.0f + expf(-v))) * (1.0f / (float)NN);
    mask[i * NN + j] = (a > 0.004f) || (i == j);
}

// ---------------------------------------------------------------------------
// GAT stage — register-tiled; parallel softmax; emits h fp32 + fp16
// ---------------------------------------------------------------------------
#define GAT_SMEM_FLOATS (2048+1024+1024+1024+64+64+64+64+16+8320+8320+16384)
#define GAT_SMEM_BYTES  (GAT_SMEM_FLOATS*4 + NN*NN)

__global__ __launch_bounds__(256) void gat_kernel(
    const float* __restrict__ X,
    const float* __restrict__ Wl, const float* __restrict__ bl,
    const float* __restrict__ Wr, const float* __restrict__ br,
    const float* __restrict__ att, const float* __restrict__ gbias,
    const float* __restrict__ Wfc, const float* __restrict__ bfc,
    const unsigned char* __restrict__ gmask,
    float* __restrict__ H, __half* __restrict__ Hf)
{
    extern __shared__ float sm[];
    float* s_x   = sm;
    float* s_wl  = s_x   + 2048;
    float* s_wr  = s_wl  + 1024;
    float* s_wfc = s_wr  + 1024;
    float* s_att = s_wfc + 1024;
    float* s_bl  = s_att + 64;
    float* s_br  = s_bl  + 64;
    float* s_gb  = s_br  + 64;
    float* s_bfc = s_gb  + 64;
    float* s_xl  = s_bfc + 16;          // 128*65
    float* s_xr  = s_xl  + 8320;        // 128*65 ; reused as "out"
    float* s_e   = s_xr  + 8320;        // 128*128
    unsigned char* s_mask = (unsigned char*)(s_e + 16384);

    const int tid = threadIdx.x;
    const int r   = blockIdx.x;
    const float* xg = X + (size_t)r * (NN * F_IN);

    for (int i = tid; i < 2048; i += 256) s_x[i] = xg[i];
    for (int i = tid; i < 1024; i += 256) { s_wl[i] = Wl[i]; s_wr[i] = Wr[i]; s_wfc[i] = Wfc[i]; }
    if (tid < 64) { s_att[tid] = att[tid]; s_bl[tid] = bl[tid]; s_br[tid] = br[tid]; s_gb[tid] = gbias[tid]; }
    if (tid < 16) s_bfc[tid] = bfc[tid];
    for (int i = tid * 4; i < NN * NN; i += 256 * 4)
        *(uint32_t*)(s_mask + i) = *(const uint32_t*)(gmask + i);
    __syncthreads();

    for (int idx = tid; idx < 8192; idx += 256) {
        int i = idx >> 6, h = idx & 63;
        const float* xi = s_x + i * 16;
        float a = s_bl[h], b = s_br[h];
        #pragma unroll
        for (int f = 0; f < 16; f++) {
            float xv = xi[f];
            a += xv * s_wl[f * 64 + h];
            b += xv * s_wr[f * 64 + h];
        }
        s_xl[i * 65 + h] = a;
        s_xr[i * 65 + h] = b;
    }
    __syncthreads();

    // e[i][j] — 8x8 per-thread register tile
    {
        const int ib = tid >> 4;
        const int jb = tid & 15;
        float acc[8][8];
        #pragma unroll
        for (int a = 0; a < 8; a++)
            #pragma unroll
            for (int b = 0; b < 8; b++) acc[a][b] = 0.f;

        for (int h = 0; h < 64; h++) {
            float av = s_att[h];
            float xls[8], xrs[8];
            #pragma unroll
            for (int u = 0; u < 8; u++) xls[u] = s_xl[(ib + u * 16) * 65 + h];
            #pragma unroll
            for (int u = 0; u < 8; u++) xrs[u] = s_xr[(jb + u * 16) * 65 + h];
            #pragma unroll
            for (int ii = 0; ii < 8; ii++)
                #pragma unroll
                for (int jj = 0; jj < 8; jj++) {
                    float v = xls[ii] + xrs[jj];
                    v = (v > 0.f) ? v : 0.2f * v;
                    acc[ii][jj] = fmaf(av, v, acc[ii][jj]);
                }
        }
        #pragma unroll
        for (int ii = 0; ii < 8; ii++) {
            int i = ib + ii * 16;
            #pragma unroll
            for (int jj = 0; jj < 8; jj++) {
                int j = jb + jj * 16;
                s_e[i * 128 + j] = s_mask[i * 128 + j] ? acc[ii][jj] : -1e9f;
            }
        }
    }
    __syncthreads();

    // softmax over i per column j — 2 threads per column + shfl pair-reduce
    {
        const int j  = tid >> 1;
        const int hf = tid & 1;
        const int i0 = hf * 64;
        float m = -1e30f;
        for (int i = i0; i < i0 + 64; i++) m = fmaxf(m, s_e[i * 128 + j]);
        m = fmaxf(m, __shfl_xor_sync(0xffffffffu, m, 1));
        float s = 0.f;
        for (int i = i0; i < i0 + 64; i++) {
            float ev = __expf(s_e[i * 128 + j] - m);
            s_e[i * 128 + j] = ev;
            s += ev;
        }
        s += __shfl_xor_sync(0xffffffffu, s, 1);
        float inv = 1.0f / s;
        for (int i = i0; i < i0 + 64; i++) s_e[i * 128 + j] *= inv;
    }
    __syncthreads();

    // out[j][h] -> s_xr
    {
        const int hb = (tid & 15) * 4;
        const int jb = tid >> 4;
        float acc[8][4];
        #pragma unroll
        for (int a = 0; a < 8; a++)
            #pragma unroll
            for (int b = 0; b < 4; b++) acc[a][b] = 0.f;

        for (int i = 0; i < 128; i++) {
            float xv[4];
            #pragma unroll
            for (int u = 0; u < 4; u++) xv[u] = s_xl[i * 65 + hb + u];
            #pragma unroll
            for (int jj = 0; jj < 8; jj++) {
                float a = s_e[i * 128 + jb + jj * 16];
                #pragma unroll
                for (int u = 0; u < 4; u++)
                    acc[jj][u] = fmaf(a, xv[u], acc[jj][u]);
            }
        }
        __syncthreads();
        #pragma unroll
        for (int jj = 0; jj < 8; jj++) {
            int j = jb + jj * 16;
            #pragma unroll
            for (int u = 0; u < 4; u++)
                s_xr[j * 65 + hb + u] = acc[jj][u] + s_gb[hb + u];
        }
    }
    __syncthreads();

    // y = out @ Wfc + bfc -> H fp32 + fp16
    {
        const int j  = tid >> 1;
        const int s0 = (tid & 1) * 8;
        float acc[8];
        #pragma unroll
        for (int u = 0; u < 8; u++) acc[u] = s_bfc[s0 + u];
        const float* oj = s_xr + j * 65;
        for (int h = 0; h < 64; h++) {
            float ov = oj[h];
            const float4 w0 = *(const float4*)&s_wfc[h * 16 + s0];
            const float4 w1 = *(const float4*)&s_wfc[h * 16 + s0 + 4];
            acc[0] = fmaf(ov, w0.x, acc[0]); acc[1] = fmaf(ov, w0.y, acc[1]);
            acc[2] = fmaf(ov, w0.z, acc[2]); acc[3] = fmaf(ov, w0.w, acc[3]);
            acc[4] = fmaf(ov, w1.x, acc[4]); acc[5] = fmaf(ov, w1.y, acc[5]);
            acc[6] = fmaf(ov, w1.z, acc[6]); acc[7] = fmaf(ov, w1.w, acc[7]);
        }
        size_t base = (size_t)r * DD + j * 16 + s0;
        #pragma unroll
        for (int u = 0; u < 8; u++) H[base + u] = acc[u];
        #pragma unroll
        for (int u = 0; u < 8; u++) Hf[base + u] = __float2half(acc[u]);
    }
}

// ---------------------------------------------------------------------------
// Weight transpose to fp16 — all 12 matrices, one launch; __half2 stores
// ---------------------------------------------------------------------------
struct TsplitArgs { const float* w[12]; };

__global__ __launch_bounds__(256) void tsplit_all_kernel(
    TsplitArgs args, __half* __restrict__ TBase)
{
    __shared__ float t[32][33];
    const int slot = blockIdx.z;
    const float* W = args.w[slot];
    __half* T = TBase + (size_t)slot * DSZ;

    const int bx = blockIdx.x, by = blockIdx.y;
    const int tx = threadIdx.x & 31, ty = threadIdx.x >> 5;
    #pragma unroll
    for (int i = 0; i < 4; i++) {
        int k = by * 32 + ty + i * 8;
        t[ty + i * 8][tx] = W[(size_t)k * 2048 + bx * 32 + tx];
    }
    __syncthreads();
    const int sx = threadIdx.x & 15;   // k-pair index
    const int sy = threadIdx.x >> 4;   // 0..15
    #pragma unroll
    for (int i = 0; i < 2; i++) {
        int n  = bx * 32 + sy + i * 16;
        int k0 = by * 32 + sx * 2;
        __half2 hv;
        hv.x = __float2half(t[sx * 2][sy + i * 16]);
        hv.y = __float2half(t[sx * 2 + 1][sy + i * 16]);
        *(__half2*)(T + (size_t)n * 2048 + k0) = hv;
    }
}

// ---------------------------------------------------------------------------
// fp16 GEMM via mma.sync — 256 threads, 8 warps, warp tile 32x64
// (R8-proven geometry), BK=64, 2-stage cp.async pipeline.
//   mode 0: C=acc+bias fp32 | 2: +resid fp32 | 3: relu->fp16 | 4: fp16
// ---------------------------------------------------------------------------
#define GEMM_THREADS   256
#define GEMM_BK        64
#define GEMM_LDS       72                       // padded row (elements)
#define GEMM_ARR_BYTES (128*GEMM_LDS*2)         // 18432
#define GEMM_STAGE     (2*GEMM_ARR_BYTES)       // 36864
#define GEMM_SMEM      (2*GEMM_STAGE)           // 73728

__device__ __forceinline__ void gemm_load_stage(
    const __half* A, const __half* B,
    uint32_t sbase, int buf, int m0, int n0, int kc, int tid)
{
    uint32_t sb = sbase + buf * GEMM_STAGE;
    const char* ga = (const char*)(A + (size_t)m0 * 2048 + kc);
    const char* gb = (const char*)(B + (size_t)n0 * 2048 + kc);
    // 128 rows x 8 chunks(16B) = 1024 chunks per array; 256 threads -> 4 each
    #pragma unroll
    for (int j = 0; j < 4; j++) {
        int idx = tid + j * 256;           // 0..1023
        int row = idx >> 3;                // 0..127
        int cu  = idx & 7;
        uint32_t soff = row * (GEMM_LDS * 2) + cu * 16;
        size_t  goff = (size_t)row * 4096 + cu * 16;
        CP_ASYNC16(sb + soff, ga + goff);
        CP_ASYNC16(sb + GEMM_ARR_BYTES + soff, gb + goff);
    }
}

__global__ __launch_bounds__(GEMM_THREADS, 1)
void gemm_mma_kernel(
    const __half* __restrict__ A, const __half* __restrict__ B,
    const float* __restrict__ bias, const float* __restrict__ resid,
    float* __restrict__ C, __half* __restrict__ Of,
    int mode)
{
    extern __shared__ char dsm[];
    const uint32_t sbase = smem_u32(dsm);

    const int tid  = threadIdx.x;
    const int wid  = tid >> 5;
    const int lane = tid & 31;
    const int wm   = wid & 3;          // m offset 32*wm
    const int wn   = wid >> 2;         // 0..1, n offset 64*wn
    const int m0   = blockIdx.y * 128;
    const int n0   = blockIdx.x * 128;

    const int aoff = (wm * 32 + (lane & 15)) * GEMM_LDS + (lane >> 4) * 8;
    const int boff = (wn * 64 + (lane >> 4) * 8 + (lane & 7)) * GEMM_LDS + ((lane >> 3) & 1) * 8;

    float acc[2][8][4];
    #pragma unroll
    for (int mt = 0; mt < 2; mt++)
        #pragma unroll
        for (int nt = 0; nt < 8; nt++)
            #pragma unroll
            for (int c = 0; c < 4; c++) acc[mt][nt][c] = 0.f;

    gemm_load_stage(A, B, sbase, 0, m0, n0, 0, tid);
    CP_COMMIT();
    CP_WAIT0();
    __syncthreads();

    const int NCHUNK = 2048 / GEMM_BK;   // 32
    for (int i = 0; i < NCHUNK; i++) {
        const int buf = i & 1;
        if (i + 1 < NCHUNK) {
            gemm_load_stage(A, B, sbase, buf ^ 1, m0, n0, (i + 1) * GEMM_BK, tid);
            CP_COMMIT();
        }

        const uint32_t aB = sbase + buf * GEMM_STAGE;
        const uint32_t bB = aB + GEMM_ARR_BYTES;

        #pragma unroll
        for (int kt = 0; kt < 4; kt++) {
            uint32_t af[2][4];
            #pragma unroll
            for (int mt = 0; mt < 2; mt++) {
                uint32_t ao = (aoff + mt * 16 * GEMM_LDS + kt * 16) * 2;
                ldsm_x4(af[mt], aB + ao);
            }
            #pragma unroll
            for (int np = 0; np < 4; np++) {
                uint32_t bo = (boff + np * 16 * GEMM_LDS + kt * 16) * 2;
                uint32_t bf[4];
                ldsm_x4(bf, bB + bo);
                #pragma unroll
                for (int half = 0; half < 2; half++) {
                    int nt = np * 2 + half;
                    #pragma unroll
                    for (int mt = 0; mt < 2; mt++)
                        mma_fp16(acc[mt][nt], af[mt], bf + half * 2);
                }
            }
        }

        CP_WAIT0();
        __syncthreads();
    }

    // epilogue
    const int g  = lane >> 2;
    const int t2 = lane & 3;
    #pragma unroll
    for (int mt = 0; mt < 2; mt++) {
        #pragma unroll
        for (int nt = 0; nt < 8; nt++) {
            int row = m0 + wm * 32 + mt * 16 + g;
            int col = n0 + wn * 64 + nt * 8 + t2 * 2;
            float b0 = __ldg(bias + col), b1 = __ldg(bias + col + 1);
            #pragma unroll
            for (int half = 0; half < 2; half++) {
                int rr = row + half * 8;
                float v0 = acc[mt][nt][half * 2 + 0] + b0;
                float v1 = acc[mt][nt][half * 2 + 1] + b1;
                size_t off = (size_t)rr * 2048 + col;
                if (mode >= 3) {
                    if (mode == 3) { v0 = fmaxf(v0, 0.f); v1 = fmaxf(v1, 0.f); }
                    __half2 hp; hp.x = __float2half(v0); hp.y = __float2half(v1);
                    *(uint32_t*)(Of + off) = *(uint32_t*)&hp;
                } else {
                    if (mode == 2) {
                        const float2 rp = *(const float2*)(resid + off);
                        v0 += rp.x; v1 += rp.y;
                    }
                    float2 o; o.x = v0; o.y = v1;
                    *(float2*)(C + off) = o;
                }
            }
        }
    }
}

// ---------------------------------------------------------------------------
// Attention — fp16 in, register-tiled, parallel softmax, fp16 out
// ---------------------------------------------------------------------------
#define ATTN_SMEM_BYTES ((8256 + 8256 + 8192 + 4160) * 4)

__global__ __launch_bounds__(256) void attn_kernel(
    const __half* __restrict__ Qf, const __half* __restrict__ Kf,
    const __half* __restrict__ Vf, __half* __restrict__ AOf)
{
    extern __shared__ float sm[];
    float* sq = sm;            // 64*129
    float* sk = sq + 8256;     // 64*129
    float* sv = sk + 8256;     // 64*128
    float* sc = sv + 8192;     // 64*65

    const int tid = threadIdx.x;
    const int b   = blockIdx.x >> 4;
    const int hd  = blockIdx.x & 15;
    const size_t base = (size_t)(b * TT) * DD + hd * DH;
    const float SCALE = 0.08838834764831845f;   // 1/sqrt(128)

    for (int idx = tid; idx < 8192; idx += 256) {
        int t = idx >> 7, d = idx & 127;
        size_t g = base + (size_t)t * DD + d;
        sq[t * 129 + d] = __half2float(Qf[g]) * SCALE;
        sk[t * 129 + d] = __half2float(Kf[g]);
        sv[idx]         = __half2float(Vf[g]);
    }
    __syncthreads();

    // scores: 4x4 per thread
    {
        const int a    = tid >> 4;
        const int bcol = tid & 15;
        float acc[4][4];
        #pragma unroll
        for (int u = 0; u < 4; u++)
            #pragma unroll
            for (int w = 0; w < 4; w++) acc[u][w] = 0.f;

        for (int d = 0; d < 128; d++) {
            float qv[4], kv[4];
            #pragma unroll
            for (int u = 0; u < 4; u++) qv[u] = sq[(a + u * 16) * 129 + d];
            #pragma unroll
            for (int w = 0; w < 4; w++) kv[w] = sk[(bcol + w * 16) * 129 + d];
            #pragma unroll
            for (int u = 0; u < 4; u++)
                #pragma unroll
                for (int w = 0; w < 4; w++)
                    acc[u][w] = fmaf(qv[u], kv[w], acc[u][w]);
        }
        #pragma unroll
        for (int u = 0; u < 4; u++)
            #pragma unroll
            for (int w = 0; w < 4; w++)
                sc[(a + u * 16) * 65 + bcol + w * 16] = acc[u][w];
    }
    __syncthreads();

    // row softmax: 4 threads per row (quad shuffles)
    {
        const int row  = tid >> 2;
        const int part = tid & 3;
        float* rp = sc + row * 65 + part * 16;
        float m = -1e30f;
        #pragma unroll
        for (int i = 0; i < 16; i++) m = fmaxf(m, rp[i]);
        m = fmaxf(m, __shfl_xor_sync(0xffffffffu, m, 1));
        m = fmaxf(m, __shfl_xor_sync(0xffffffffu, m, 2));
        float s = 0.f;
        #pragma unroll
        for (int i = 0; i < 16; i++) { float e = __expf(rp[i] - m); rp[i] = e; s += e; }
        s += __shfl_xor_sync(0xffffffffu, s, 1);
        s += __shfl_xor_sync(0xffffffffu, s, 2);
        float inv = 1.0f / s;
        #pragma unroll
        for (int i = 0; i < 16; i++) rp[i] *= inv;
    }
    __syncthreads();

    // ao: 8 t x 4 d per thread
    {
        const int tg = tid >> 5;
        const int dg = tid & 31;
        float acc[8][4];
        #pragma unroll
        for (int u = 0; u < 8; u++)
            #pragma unroll
            for (int dd = 0; dd < 4; dd++) acc[u][dd] = 0.f;

        for (int t2 = 0; t2 < 64; t2++) {
            float av[8], vv[4];
            #pragma unroll
            for (int u = 0; u < 8; u++) av[u] = sc[(tg * 8 + u) * 65 + t2];
            #pragma unroll
            for (int dd = 0; dd < 4; dd++) vv[dd] = sv[t2 * 128 + dg + dd * 32];
            #pragma unroll
            for (int u = 0; u < 8; u++)
                #pragma unroll
                for (int dd = 0; dd < 4; dd++)
                    acc[u][dd] = fmaf(av[u], vv[dd], acc[u][dd]);
        }
        #pragma unroll
        for (int u = 0; u < 8; u++) {
            int t = tg * 8 + u;
            #pragma unroll
            for (int dd = 0; dd < 4; dd++)
                AOf[base + (size_t)t * DD + dg + dd * 32] = __float2half(acc[u][dd]);
        }
    }
}

// ---------------------------------------------------------------------------
// LayerNorm: fp32 out + fp16 out
// ---------------------------------------------------------------------------
__global__ __launch_bounds__(256) void ln_kernel(
    const float* __restrict__ x, float* __restrict__ y,
    const float* __restrict__ g, const float* __restrict__ b,
    __half* __restrict__ Yf)
{
    __shared__ float red[256];
    const int row = blockIdx.x, tid = threadIdx.x;
    const float* xr = x + (size_t)row * DD;

    float s = 0.f;
    for (int i = tid; i < DD; i += 256) s += xr[i];
    red[tid] = s; __syncthreads();
    for (int st = 128; st > 0; st >>= 1) { if (tid < st) red[tid] += red[tid + st]; __syncthreads(); }
    float mu = red[0] * (1.0f / DD);
    __syncthreads();

    float v = 0.f;
    for (int i = tid; i < DD; i += 256) { float d = xr[i] - mu; v += d * d; }
    red[tid] = v; __syncthreads();
    for (int st = 128; st > 0; st >>= 1) { if (tid < st) red[tid] += red[tid + st]; __syncthreads(); }
    float var = red[0] * (1.0f / DD);
    float inv = 1.0f / sqrtf(var + 1e-5f);

    float* yr = y + (size_t)row * DD;
    __half* fr = Yf + (size_t)row * DD;
    for (int i = tid; i < DD; i += 256) {
        float val = (xr[i] - mu) * inv * g[i] + b[i];
        yr[i] = val;
        fr[i] = __float2half(val);
    }
}

// ---------------------------------------------------------------------------
// Final projection
// ---------------------------------------------------------------------------
__global__ void out_kernel(const float* __restrict__ H, const float* __restrict__ Wout,
                           const float* __restrict__ bout, float* __restrict__ out)
{
    int b = blockIdx.x;
    int o = threadIdx.x >> 5;
    int lane = threadIdx.x & 31;
    if (o >= NOUT) return;
    const float* h = H + (size_t)(b * TT + TT - 1) * DD;
    float acc = 0.f;
    for (int i = lane; i < DD; i += 32)
        acc += h[i] * Wout[i * NOUT + o];
    #pragma unroll
    for (int s = 16; s > 0; s >>= 1)
        acc += __shfl_down_sync(0xffffffffu, acc, s);
    if (lane == 0) out[b * NOUT + o] = acc + bout[o];
}

// ---------------------------------------------------------------------------
// Launch
// ---------------------------------------------------------------------------
extern "C" void kernel_launch(void* const* d_in, const int* in_sizes, int n_in,
                              void* d_out, int out_size)
{
    (void)in_sizes; (void)n_in; (void)out_size;

    const float* X      = (const float*)d_in[0];
    const float* V_Adap = (const float*)d_in[1];
    const float* Wl     = (const float*)d_in[2];
    const float* bl     = (const float*)d_in[3];
    const float* Wr     = (const float*)d_in[4];
    const float* br     = (const float*)d_in[5];
    const float* att    = (const float*)d_in[6];
    const float* gbias  = (const float*)d_in[7];
    const float* Wfc    = (const float*)d_in[8];
    const float* bfc    = (const float*)d_in[9];
    const float* Wq     = (const float*)d_in[10];
    const float* bq     = (const float*)d_in[11];
    const float* Wk     = (const float*)d_in[12];
    const float* bk     = (const float*)d_in[13];
    const float* Wv     = (const float*)d_in[14];
    const float* bv     = (const float*)d_in[15];
    const float* Wo     = (const float*)d_in[16];
    const float* bo     = (const float*)d_in[17];
    const float* ln1g   = (const float*)d_in[18];
    const float* ln1b   = (const float*)d_in[19];
    const float* W1     = (const float*)d_in[20];
    const float* b1     = (const float*)d_in[21];
    const float* W2     = (const float*)d_in[22];
    const float* b2     = (const float*)d_in[23];
    const float* ln2g   = (const float*)d_in[24];
    const float* ln2b   = (const float*)d_in[25];
    const float* Wout   = (const float*)d_in[26];
    const float* bout   = (const float*)d_in[27];
    const int*   cls    = (const int*)d_in[28];

    float* base = nullptr;
    unsigned char* maskp = nullptr;
    __half *wt = nullptr, *af = nullptr, *bf = nullptr;
    cudaGetSymbolAddress((void**)&base,  g_scratch);
    cudaGetSymbolAddress((void**)&maskp, g_mask);
    cudaGetSymbolAddress((void**)&wt,    g_wt);
    cudaGetSymbolAddress((void**)&af,    g_a);
    cudaGetSymbolAddress((void**)&bf,    g_b);

    float* h  = base + 0ull * DSZ;
    float* t  = base + 6ull * DSZ;
    __half* qh = (__half*)(base + 1ull * DSZ);
    __half* kh = qh + DSZ;
    __half* vh = kh + DSZ;

    cudaFuncSetAttribute(gat_kernel,      cudaFuncAttributeMaxDynamicSharedMemorySize, GAT_SMEM_BYTES);
    cudaFuncSetAttribute(attn_kernel,     cudaFuncAttributeMaxDynamicSharedMemorySize, ATTN_SMEM_BYTES);
    cudaFuncSetAttribute(gemm_mma_kernel, cudaFuncAttributeMaxDynamicSharedMemorySize, GEMM_SMEM);

    mask_kernel<<<NN, NN>>>(V_Adap, cls, maskp);
    gat_kernel<<<ROWS, 256, GAT_SMEM_BYTES>>>(X, Wl, bl, Wr, br, att, gbias, Wfc, bfc, maskp,
                                              h, af);

    // transpose all 12 weight matrices to fp16 in ONE launch
    {
        TsplitArgs ta;
        for (int l = 0; l < LAYERS; l++) {
            ta.w[l * 6 + 0] = Wq + (size_t)l * DSZ;
            ta.w[l * 6 + 1] = Wk + (size_t)l * DSZ;
            ta.w[l * 6 + 2] = Wv + (size_t)l * DSZ;
            ta.w[l * 6 + 3] = Wo + (size_t)l * DSZ;
            ta.w[l * 6 + 4] = W1 + (size_t)l * DSZ;
            ta.w[l * 6 + 5] = W2 + (size_t)l * DSZ;
        }
        dim3 tg(64, 64, 12);
        tsplit_all_kernel<<<tg, 256>>>(ta, wt);
    }

    dim3 gg(16, 16);
    for (int l = 0; l < LAYERS; l++) {
        __half* w0  = wt + (size_t)(l * 6 + 0) * DSZ;
        __half* w1p = wt + (size_t)(l * 6 + 1) * DSZ;
        __half* w2p = wt + (size_t)(l * 6 + 2) * DSZ;
        __half* w3  = wt + (size_t)(l * 6 + 3) * DSZ;
        __half* w4  = wt + (size_t)(l * 6 + 4) * DSZ;
        __half* w5  = wt + (size_t)(l * 6 + 5) * DSZ;

        gemm_mma_kernel<<<gg, GEMM_THREADS, GEMM_SMEM>>>(af, w0, bq + l * DD,
                                                nullptr, nullptr, qh, 4);
        gemm_mma_kernel<<<gg, GEMM_THREADS, GEMM_SMEM>>>(af, w1p, bk + l * DD,
                                                nullptr, nullptr, kh, 4);
        gemm_mma_kernel<<<gg, GEMM_THREADS, GEMM_SMEM>>>(af, w2p, bv + l * DD,
                                                nullptr, nullptr, vh, 4);
        attn_kernel<<<BB * NHEADS, 256, ATTN_SMEM_BYTES>>>(qh, kh, vh, af);
        gemm_mma_kernel<<<gg, GEMM_THREADS, GEMM_SMEM>>>(af, w3, bo + l * DD,
                                                h, t, nullptr, 2);
        ln_kernel<<<ROWS, 256>>>(t, h, ln1g + l * DD, ln1b + l * DD, af);
        gemm_mma_kernel<<<gg, GEMM_THREADS, GEMM_SMEM>>>(af, w4, b1 + l * DFF,
                                                nullptr, nullptr, bf, 3);
        gemm_mma_kernel<<<gg, GEMM_THREADS, GEMM_SMEM>>>(bf, w5, b2 + l * DD,
                                                h, t, nullptr, 2);
        ln_kernel<<<ROWS, 256>>>(t, h, ln2g + l * DD, ln2b + l * DD, af);
    }

    out_kernel<<<BB, 320>>>(h, Wout, bout, (float*)d_out);
}

// round 16
// speedup vs baseline: 1.0300x; 1.0300x over previous
#include <cuda_runtime.h>
#include <cuda_fp16.h>
#include <math.h>
#include <stdint.h>

// ---------------------------------------------------------------------------
// Shapes
// ---------------------------------------------------------------------------
#define BB     32
#define TT     64
#define NN     128
#define F_IN   16
#define SOUT   16
#define DD     2048
#define NHEADS 16
#define DH     128
#define DFF    2048
#define LAYERS 2
#define NOUT   10
#define ROWS   (BB*TT)
#define DSZ    (ROWS*DD)        // 4M elements; one 2048x2048 matrix

// ---------------------------------------------------------------------------
// Static scratch (allocation-free rule)
// ---------------------------------------------------------------------------
__device__ float g_scratch[7ull * DSZ];                 // h,(qkv fp16),-,-,-,tmp
__device__ unsigned char g_mask[NN * NN];
__device__ __half g_wt[12ull * DSZ];                    // transposed weights fp16
__device__ __half g_a[DSZ];                             // activation fp16 (A)
__device__ __half g_b[DSZ];                             // activation fp16 (B, FFN mid)

// ---------------------------------------------------------------------------
// Helpers
// ---------------------------------------------------------------------------
__device__ __forceinline__ uint32_t smem_u32(const void* p) {
    uint32_t a;
    asm("{ .reg .u64 t; cvta.to.shared.u64 t, %1; cvt.u32.u64 %0, t; }" : "=r"(a) : "l"(p));
    return a;
}

#define CP_ASYNC16(saddr, gptr) \
    asm volatile("cp.async.cg.shared.global [%0], [%1], 16;" :: "r"(saddr), "l"(gptr) : "memory")
#define CP_COMMIT()  asm volatile("cp.async.commit_group;" ::: "memory")
#define CP_WAIT0()   asm volatile("cp.async.wait_group 0;" ::: "memory")

__device__ __forceinline__ void ldsm_x4(uint32_t* r, uint32_t addr) {
    asm volatile("ldmatrix.sync.aligned.m8n8.x4.shared.b16 {%0,%1,%2,%3}, [%4];"
                 : "=r"(r[0]), "=r"(r[1]), "=r"(r[2]), "=r"(r[3]) : "r"(addr));
}
__device__ __forceinline__ void mma_fp16(float* d, const uint32_t* a, const uint32_t* b) {
    asm volatile(
        "mma.sync.aligned.m16n8k16.row.col.f32.f16.f16.f32 "
        "{%0,%1,%2,%3}, {%4,%5,%6,%7}, {%8,%9}, {%0,%1,%2,%3};"
        : "+f"(d[0]), "+f"(d[1]), "+f"(d[2]), "+f"(d[3])
        : "r"(a[0]), "r"(a[1]), "r"(a[2]), "r"(a[3]), "r"(b[0]), "r"(b[1]));
}

// ---------------------------------------------------------------------------
// Mask kernel
// ---------------------------------------------------------------------------
__global__ void mask_kernel(const float* __restrict__ V, const int* __restrict__ cls,
                            unsigned char* __restrict__ mask)
{
    int i = blockIdx.x, j = threadIdx.x;
    int c = *cls;
    float v = V[(size_t)c * NN * NN + i * NN + j];
    float a = (1.0f / (1.0f + expf(-v))) * (1.0f / (float)NN);
    mask[i * NN + j] = (a > 0.004f) || (i == j);
}

// ---------------------------------------------------------------------------
// GAT stage — j-split: 2 blocks per (b,t) row, each handles 64 target cols.
// smem ~110KB -> 2 resident blocks/SM. Emits h fp32 + fp16.
// ---------------------------------------------------------------------------
#define GAT_SMEM_FLOATS (2048+1024+1024+1024+64+64+64+64+16+8320+4160+8192)
#define GAT_SMEM_BYTES  (GAT_SMEM_FLOATS*4 + 128*64)

__global__ __launch_bounds__(256) void gat_kernel(
    const float* __restrict__ X,
    const float* __restrict__ Wl, const float* __restrict__ bl,
    const float* __restrict__ Wr, const float* __restrict__ br,
    const float* __restrict__ att, const float* __restrict__ gbias,
    const float* __restrict__ Wfc, const float* __restrict__ bfc,
    const unsigned char* __restrict__ gmask,
    float* __restrict__ H, __half* __restrict__ Hf)
{
    extern __shared__ float sm[];
    float* s_x   = sm;                  // 128*16
    float* s_wl  = s_x   + 2048;        // 16*64
    float* s_wr  = s_wl  + 1024;
    float* s_wfc = s_wr  + 1024;        // 64*16
    float* s_att = s_wfc + 1024;
    float* s_bl  = s_att + 64;
    float* s_br  = s_bl  + 64;
    float* s_gb  = s_br  + 64;
    float* s_bfc = s_gb  + 64;
    float* s_xl  = s_bfc + 16;          // 128*65 (full sources)
    float* s_xr  = s_xl  + 8320;        // 64*65 (this block's j-half); reused as out
    float* s_e   = s_xr  + 4160;        // 128*64 (e[i][j_local])
    unsigned char* s_mask = (unsigned char*)(s_e + 8192);   // 128*64 bytes

    const int tid = threadIdx.x;
    const int r   = blockIdx.x >> 1;    // token row
    const int jh  = blockIdx.x & 1;     // j half
    const int j0  = jh * 64;
    const float* xg = X + (size_t)r * (NN * F_IN);

    for (int i = tid; i < 2048; i += 256) s_x[i] = xg[i];
    for (int i = tid; i < 1024; i += 256) { s_wl[i] = Wl[i]; s_wr[i] = Wr[i]; s_wfc[i] = Wfc[i]; }
    if (tid < 64) { s_att[tid] = att[tid]; s_bl[tid] = bl[tid]; s_br[tid] = br[tid]; s_gb[tid] = gbias[tid]; }
    if (tid < 16) s_bfc[tid] = bfc[tid];
    // mask half: s_mask[i*64+jl] = gmask[i*128 + j0 + jl] (4B words)
    {
        uint32_t* sm32 = (uint32_t*)s_mask;
        const uint32_t* gm32 = (const uint32_t*)gmask;
        for (int idx = tid; idx < 2048; idx += 256) {
            int i = idx >> 4, w = idx & 15;
            sm32[i * 16 + w] = gm32[i * 32 + (j0 >> 2) + w];
        }
    }
    __syncthreads();

    // xl: all 128 source rows
    for (int idx = tid; idx < 8192; idx += 256) {
        int i = idx >> 6, h = idx & 63;
        const float* xi = s_x + i * 16;
        float a = s_bl[h];
        #pragma unroll
        for (int f = 0; f < 16; f++) a += xi[f] * s_wl[f * 64 + h];
        s_xl[i * 65 + h] = a;
    }
    // xr: only this block's 64 target rows
    for (int idx = tid; idx < 4096; idx += 256) {
        int jl = idx >> 6, h = idx & 63;
        const float* xj = s_x + (j0 + jl) * 16;
        float b = s_br[h];
        #pragma unroll
        for (int f = 0; f < 16; f++) b += xj[f] * s_wr[f * 64 + h];
        s_xr[jl * 65 + h] = b;
    }
    __syncthreads();

    // e[i][jl] — 8i x 4j per-thread register tile
    {
        const int ib = tid >> 4;     // i = ib + u*16, u<8
        const int jb = tid & 15;     // jl = jb + w*16, w<4
        float acc[8][4];
        #pragma unroll
        for (int a = 0; a < 8; a++)
            #pragma unroll
            for (int b = 0; b < 4; b++) acc[a][b] = 0.f;

        for (int h = 0; h < 64; h++) {
            float av = s_att[h];
            float xls[8], xrs[4];
            #pragma unroll
            for (int u = 0; u < 8; u++) xls[u] = s_xl[(ib + u * 16) * 65 + h];
            #pragma unroll
            for (int w = 0; w < 4; w++) xrs[w] = s_xr[(jb + w * 16) * 65 + h];
            #pragma unroll
            for (int u = 0; u < 8; u++)
                #pragma unroll
                for (int w = 0; w < 4; w++) {
                    float v = xls[u] + xrs[w];
                    v = fmaxf(v, 0.2f * v);
                    acc[u][w] = fmaf(av, v, acc[u][w]);
                }
        }
        #pragma unroll
        for (int u = 0; u < 8; u++) {
            int i = ib + u * 16;
            #pragma unroll
            for (int w = 0; w < 4; w++) {
                int jl = jb + w * 16;
                s_e[i * 64 + jl] = s_mask[i * 64 + jl] ? acc[u][w] : -1e9f;
            }
        }
    }
    __syncthreads();

    // softmax over i per column jl — 4 threads per column (quad shuffles)
    {
        const int col  = tid >> 2;   // 0..63
        const int part = tid & 3;    // i in [part*32, part*32+32)
        const int i0   = part * 32;
        float m = -1e30f;
        for (int i = i0; i < i0 + 32; i++) m = fmaxf(m, s_e[i * 64 + col]);
        m = fmaxf(m, __shfl_xor_sync(0xffffffffu, m, 1));
        m = fmaxf(m, __shfl_xor_sync(0xffffffffu, m, 2));
        float s = 0.f;
        for (int i = i0; i < i0 + 32; i++) {
            float ev = __expf(s_e[i * 64 + col] - m);
            s_e[i * 64 + col] = ev;
            s += ev;
        }
        s += __shfl_xor_sync(0xffffffffu, s, 1);
        s += __shfl_xor_sync(0xffffffffu, s, 2);
        float inv = 1.0f / s;
        for (int i = i0; i < i0 + 32; i++) s_e[i * 64 + col] *= inv;
    }
    __syncthreads();

    // out[jl][h] = sum_i alpha[i][jl]*xl[i][h] + gb[h] -> s_xr (reuse, 64x65)
    {
        const int jb = tid >> 4;          // jl = jb + jj*16, jj<4
        const int hb = (tid & 15) * 4;    // 4 h values
        float acc[4][4];
        #pragma unroll
        for (int a = 0; a < 4; a++)
            #pragma unroll
            for (int b = 0; b < 4; b++) acc[a][b] = 0.f;

        for (int i = 0; i < 128; i++) {
            float xv[4];
            #pragma unroll
            for (int u = 0; u < 4; u++) xv[u] = s_xl[i * 65 + hb + u];
            #pragma unroll
            for (int jj = 0; jj < 4; jj++) {
                float a = s_e[i * 64 + jb + jj * 16];
                #pragma unroll
                for (int u = 0; u < 4; u++)
                    acc[jj][u] = fmaf(a, xv[u], acc[jj][u]);
            }
        }
        #pragma unroll
        for (int jj = 0; jj < 4; jj++) {
            int jl = jb + jj * 16;
            #pragma unroll
            for (int u = 0; u < 4; u++)
                s_xr[jl * 65 + hb + u] = acc[jj][u] + s_gb[hb + u];
        }
    }
    __syncthreads();

    // y = out @ Wfc + bfc -> H fp32 + fp16 (this block's 64 j rows)
    {
        const int jl = tid >> 2;          // 0..63
        const int s0 = (tid & 3) * 4;     // 4 outputs
        float acc[4];
        #pragma unroll
        for (int u = 0; u < 4; u++) acc[u] = s_bfc[s0 + u];
        const float* oj = s_xr + jl * 65;
        for (int h = 0; h < 64; h++) {
            float ov = oj[h];
            const float4 w = *(const float4*)&s_wfc[h * 16 + s0];
            acc[0] = fmaf(ov, w.x, acc[0]); acc[1] = fmaf(ov, w.y, acc[1]);
            acc[2] = fmaf(ov, w.z, acc[2]); acc[3] = fmaf(ov, w.w, acc[3]);
        }
        size_t base = (size_t)r * DD + (j0 + jl) * 16 + s0;
        #pragma unroll
        for (int u = 0; u < 4; u++) H[base + u] = acc[u];
        #pragma unroll
        for (int u = 0; u < 4; u++) Hf[base + u] = __float2half(acc[u]);
    }
}

// ---------------------------------------------------------------------------
// Weight transpose to fp16 — all 12 matrices, one launch; __half2 stores
// ---------------------------------------------------------------------------
struct TsplitArgs { const float* w[12]; };

__global__ __launch_bounds__(256) void tsplit_all_kernel(
    TsplitArgs args, __half* __restrict__ TBase)
{
    __shared__ float t[32][33];
    const int slot = blockIdx.z;
    const float* W = args.w[slot];
    __half* T = TBase + (size_t)slot * DSZ;

    const int bx = blockIdx.x, by = blockIdx.y;
    const int tx = threadIdx.x & 31, ty = threadIdx.x >> 5;
    #pragma unroll
    for (int i = 0; i < 4; i++) {
        int k = by * 32 + ty + i * 8;
        t[ty + i * 8][tx] = W[(size_t)k * 2048 + bx * 32 + tx];
    }
    __syncthreads();
    const int sx = threadIdx.x & 15;
    const int sy = threadIdx.x >> 4;
    #pragma unroll
    for (int i = 0; i < 2; i++) {
        int n  = bx * 32 + sy + i * 16;
        int k0 = by * 32 + sx * 2;
        __half2 hv;
        hv.x = __float2half(t[sx * 2][sy + i * 16]);
        hv.y = __float2half(t[sx * 2 + 1][sy + i * 16]);
        *(__half2*)(T + (size_t)n * 2048 + k0) = hv;
    }
}

// ---------------------------------------------------------------------------
// fp16 GEMM core (R14-proven: 512 threads, 16 warps, warp tile 32x32, BK=64)
//   mode 0: C=acc+bias fp32 | 2: +resid fp32 | 3: relu->fp16 | 4: fp16
// ---------------------------------------------------------------------------
#define GEMM_THREADS   512
#define GEMM_BK        64
#define GEMM_LDS       72
#define GEMM_ARR_BYTES (128*GEMM_LDS*2)         // 18432
#define GEMM_STAGE     (2*GEMM_ARR_BYTES)       // 36864
#define GEMM_SMEM      (2*GEMM_STAGE)           // 73728

__device__ __forceinline__ void gemm_load_stage(
    const __half* A, const __half* B,
    uint32_t sbase, int buf, int m0, int n0, int kc, int tid)
{
    uint32_t sb = sbase + buf * GEMM_STAGE;
    const char* ga = (const char*)(A + (size_t)m0 * 2048 + kc);
    const char* gb = (const char*)(B + (size_t)n0 * 2048 + kc);
    #pragma unroll
    for (int j = 0; j < 2; j++) {
        int idx = tid + j * 512;
        int row = idx >> 3;
        int cu  = idx & 7;
        uint32_t soff = row * (GEMM_LDS * 2) + cu * 16;
        size_t  goff = (size_t)row * 4096 + cu * 16;
        CP_ASYNC16(sb + soff, ga + goff);
        CP_ASYNC16(sb + GEMM_ARR_BYTES + soff, gb + goff);
    }
}

__device__ __forceinline__ void gemm_body(
    const __half* A, const __half* B,
    const float* bias, const float* resid,
    float* C, __half* Of, int mode,
    int m0, int n0, char* dsm)
{
    const uint32_t sbase = smem_u32(dsm);
    const int tid  = threadIdx.x;
    const int wid  = tid >> 5;
    const int lane = tid & 31;
    const int wm   = wid & 3;
    const int wn   = wid >> 2;

    const int aoff = (wm * 32 + (lane & 15)) * GEMM_LDS + (lane >> 4) * 8;
    const int boff = (wn * 32 + (lane >> 4) * 8 + (lane & 7)) * GEMM_LDS + ((lane >> 3) & 1) * 8;

    float acc[2][4][4];
    #pragma unroll
    for (int mt = 0; mt < 2; mt++)
        #pragma unroll
        for (int nt = 0; nt < 4; nt++)
            #pragma unroll
            for (int c = 0; c < 4; c++) acc[mt][nt][c] = 0.f;

    gemm_load_stage(A, B, sbase, 0, m0, n0, 0, tid);
    CP_COMMIT();
    CP_WAIT0();
    __syncthreads();

    const int NCHUNK = 2048 / GEMM_BK;   // 32
    for (int i = 0; i < NCHUNK; i++) {
        const int buf = i & 1;
        if (i + 1 < NCHUNK) {
            gemm_load_stage(A, B, sbase, buf ^ 1, m0, n0, (i + 1) * GEMM_BK, tid);
            CP_COMMIT();
        }

        const uint32_t aB = sbase + buf * GEMM_STAGE;
        const uint32_t bB = aB + GEMM_ARR_BYTES;

        #pragma unroll
        for (int kt = 0; kt < 4; kt++) {
            uint32_t af[2][4];
            #pragma unroll
            for (int mt = 0; mt < 2; mt++) {
                uint32_t ao = (aoff + mt * 16 * GEMM_LDS + kt * 16) * 2;
                ldsm_x4(af[mt], aB + ao);
            }
            #pragma unroll
            for (int np = 0; np < 2; np++) {
                uint32_t bo = (boff + np * 16 * GEMM_LDS + kt * 16) * 2;
                uint32_t bf[4];
                ldsm_x4(bf, bB + bo);
                #pragma unroll
                for (int half = 0; half < 2; half++) {
                    int nt = np * 2 + half;
                    #pragma unroll
                    for (int mt = 0; mt < 2; mt++)
                        mma_fp16(acc[mt][nt], af[mt], bf + half * 2);
                }
            }
        }

        CP_WAIT0();
        __syncthreads();
    }

    const int g  = lane >> 2;
    const int t2 = lane & 3;
    #pragma unroll
    for (int mt = 0; mt < 2; mt++) {
        #pragma unroll
        for (int nt = 0; nt < 4; nt++) {
            int row = m0 + wm * 32 + mt * 16 + g;
            int col = n0 + wn * 32 + nt * 8 + t2 * 2;
            float b0 = __ldg(bias + col), b1 = __ldg(bias + col + 1);
            #pragma unroll
            for (int half = 0; half < 2; half++) {
                int rr = row + half * 8;
                float v0 = acc[mt][nt][half * 2 + 0] + b0;
                float v1 = acc[mt][nt][half * 2 + 1] + b1;
                size_t off = (size_t)rr * 2048 + col;
                if (mode >= 3) {
                    if (mode == 3) { v0 = fmaxf(v0, 0.f); v1 = fmaxf(v1, 0.f); }
                    __half2 hp; hp.x = __float2half(v0); hp.y = __float2half(v1);
                    *(uint32_t*)(Of + off) = *(uint32_t*)&hp;
                } else {
                    if (mode == 2) {
                        const float2 rp = *(const float2*)(resid + off);
                        v0 += rp.x; v1 += rp.y;
                    }
                    float2 o; o.x = v0; o.y = v1;
                    *(float2*)(C + off) = o;
                }
            }
        }
    }
}

__global__ __launch_bounds__(GEMM_THREADS, 1)
void gemm_mma_kernel(
    const __half* __restrict__ A, const __half* __restrict__ B,
    const float* __restrict__ bias, const float* __restrict__ resid,
    float* __restrict__ C, __half* __restrict__ Of, int mode)
{
    extern __shared__ char dsm[];
    gemm_body(A, B, bias, resid, C, Of, mode,
              blockIdx.y * 128, blockIdx.x * 128, dsm);
}

// QKV fused: grid (16,16,3); z selects B/bias/output; mode 4 path
struct QKVArgs {
    const __half* A;
    const __half* B0; const __half* B1; const __half* B2;
    const float* bi0; const float* bi1; const float* bi2;
    __half* O0; __half* O1; __half* O2;
};

__global__ __launch_bounds__(GEMM_THREADS, 1)
void gemm_qkv_kernel(QKVArgs a)
{
    extern __shared__ char dsm[];
    const int z = blockIdx.z;
    const __half* B = (z == 0) ? a.B0 : (z == 1) ? a.B1 : a.B2;
    const float* bi = (z == 0) ? a.bi0 : (z == 1) ? a.bi1 : a.bi2;
    __half* O       = (z == 0) ? a.O0 : (z == 1) ? a.O1 : a.O2;
    gemm_body(a.A, B, bi, nullptr, nullptr, O, 4,
              blockIdx.y * 128, blockIdx.x * 128, dsm);
}

// ---------------------------------------------------------------------------
// Attention — fp16 in, register-tiled, parallel softmax, fp16 out
// ---------------------------------------------------------------------------
#define ATTN_SMEM_BYTES ((8256 + 8256 + 8192 + 4160) * 4)

__global__ __launch_bounds__(256) void attn_kernel(
    const __half* __restrict__ Qf, const __half* __restrict__ Kf,
    const __half* __restrict__ Vf, __half* __restrict__ AOf)
{
    extern __shared__ float sm[];
    float* sq = sm;            // 64*129
    float* sk = sq + 8256;     // 64*129
    float* sv = sk + 8256;     // 64*128
    float* sc = sv + 8192;     // 64*65

    const int tid = threadIdx.x;
    const int b   = blockIdx.x >> 4;
    const int hd  = blockIdx.x & 15;
    const size_t base = (size_t)(b * TT) * DD + hd * DH;
    const float SCALE = 0.08838834764831845f;

    for (int idx = tid; idx < 8192; idx += 256) {
        int t = idx >> 7, d = idx & 127;
        size_t g = base + (size_t)t * DD + d;
        sq[t * 129 + d] = __half2float(Qf[g]) * SCALE;
        sk[t * 129 + d] = __half2float(Kf[g]);
        sv[idx]         = __half2float(Vf[g]);
    }
    __syncthreads();

    {
        const int a    = tid >> 4;
        const int bcol = tid & 15;
        float acc[4][4];
        #pragma unroll
        for (int u = 0; u < 4; u++)
            #pragma unroll
            for (int w = 0; w < 4; w++) acc[u][w] = 0.f;

        for (int d = 0; d < 128; d++) {
            float qv[4], kv[4];
            #pragma unroll
            for (int u = 0; u < 4; u++) qv[u] = sq[(a + u * 16) * 129 + d];
            #pragma unroll
            for (int w = 0; w < 4; w++) kv[w] = sk[(bcol + w * 16) * 129 + d];
            #pragma unroll
            for (int u = 0; u < 4; u++)
                #pragma unroll
                for (int w = 0; w < 4; w++)
                    acc[u][w] = fmaf(qv[u], kv[w], acc[u][w]);
        }
        #pragma unroll
        for (int u = 0; u < 4; u++)
            #pragma unroll
            for (int w = 0; w < 4; w++)
                sc[(a + u * 16) * 65 + bcol + w * 16] = acc[u][w];
    }
    __syncthreads();

    {
        const int row  = tid >> 2;
        const int part = tid & 3;
        float* rp = sc + row * 65 + part * 16;
        float m = -1e30f;
        #pragma unroll
        for (int i = 0; i < 16; i++) m = fmaxf(m, rp[i]);
        m = fmaxf(m, __shfl_xor_sync(0xffffffffu, m, 1));
        m = fmaxf(m, __shfl_xor_sync(0xffffffffu, m, 2));
        float s = 0.f;
        #pragma unroll
        for (int i = 0; i < 16; i++) { float e = __expf(rp[i] - m); rp[i] = e; s += e; }
        s += __shfl_xor_sync(0xffffffffu, s, 1);
        s += __shfl_xor_sync(0xffffffffu, s, 2);
        float inv = 1.0f / s;
        #pragma unroll
        for (int i = 0; i < 16; i++) rp[i] *= inv;
    }
    __syncthreads();

    {
        const int tg = tid >> 5;
        const int dg = tid & 31;
        float acc[8][4];
        #pragma unroll
        for (int u = 0; u < 8; u++)
            #pragma unroll
            for (int dd = 0; dd < 4; dd++) acc[u][dd] = 0.f;

        for (int t2 = 0; t2 < 64; t2++) {
            float av[8], vv[4];
            #pragma unroll
            for (int u = 0; u < 8; u++) av[u] = sc[(tg * 8 + u) * 65 + t2];
            #pragma unroll
            for (int dd = 0; dd < 4; dd++) vv[dd] = sv[t2 * 128 + dg + dd * 32];
            #pragma unroll
            for (int u = 0; u < 8; u++)
                #pragma unroll
                for (int dd = 0; dd < 4; dd++)
                    acc[u][dd] = fmaf(av[u], vv[dd], acc[u][dd]);
        }
        #pragma unroll
        for (int u = 0; u < 8; u++) {
            int t = tg * 8 + u;
            #pragma unroll
            for (int dd = 0; dd < 4; dd++)
                AOf[base + (size_t)t * DD + dg + dd * 32] = __float2half(acc[u][dd]);
        }
    }
}

// ---------------------------------------------------------------------------
// LayerNorm: fp32 out + fp16 out
// ---------------------------------------------------------------------------
__global__ __launch_bounds__(256) void ln_kernel(
    const float* __restrict__ x, float* __restrict__ y,
    const float* __restrict__ g, const float* __restrict__ b,
    __half* __restrict__ Yf)
{
    __shared__ float red[256];
    const int row = blockIdx.x, tid = threadIdx.x;
    const float* xr = x + (size_t)row * DD;

    float s = 0.f;
    for (int i = tid; i < DD; i += 256) s += xr[i];
    red[tid] = s; __syncthreads();
    for (int st = 128; st > 0; st >>= 1) { if (tid < st) red[tid] += red[tid + st]; __syncthreads(); }
    float mu = red[0] * (1.0f / DD);
    __syncthreads();

    float v = 0.f;
    for (int i = tid; i < DD; i += 256) { float d = xr[i] - mu; v += d * d; }
    red[tid] = v; __syncthreads();
    for (int st = 128; st > 0; st >>= 1) { if (tid < st) red[tid] += red[tid + st]; __syncthreads(); }
    float var = red[0] * (1.0f / DD);
    float inv = 1.0f / sqrtf(var + 1e-5f);

    float* yr = y + (size_t)row * DD;
    __half* fr = Yf + (size_t)row * DD;
    for (int i = tid; i < DD; i += 256) {
        float val = (xr[i] - mu) * inv * g[i] + b[i];
        yr[i] = val;
        fr[i] = __float2half(val);
    }
}

// ---------------------------------------------------------------------------
// Final projection
// ---------------------------------------------------------------------------
__global__ void out_kernel(const float* __restrict__ H, const float* __restrict__ Wout,
                           const float* __restrict__ bout, float* __restrict__ out)
{
    int b = blockIdx.x;
    int o = threadIdx.x >> 5;
    int lane = threadIdx.x & 31;
    if (o >= NOUT) return;
    const float* h = H + (size_t)(b * TT + TT - 1) * DD;
    float acc = 0.f;
    for (int i = lane; i < DD; i += 32)
        acc += h[i] * Wout[i * NOUT + o];
    #pragma unroll
    for (int s = 16; s > 0; s >>= 1)
        acc += __shfl_down_sync(0xffffffffu, acc, s);
    if (lane == 0) out[b * NOUT + o] = acc + bout[o];
}

// ---------------------------------------------------------------------------
// Launch
// ---------------------------------------------------------------------------
extern "C" void kernel_launch(void* const* d_in, const int* in_sizes, int n_in,
                              void* d_out, int out_size)
{
    (void)in_sizes; (void)n_in; (void)out_size;

    const float* X      = (const float*)d_in[0];
    const float* V_Adap = (const float*)d_in[1];
    const float* Wl     = (const float*)d_in[2];
    const float* bl     = (const float*)d_in[3];
    const float* Wr     = (const float*)d_in[4];
    const float* br     = (const float*)d_in[5];
    const float* att    = (const float*)d_in[6];
    const float* gbias  = (const float*)d_in[7];
    const float* Wfc    = (const float*)d_in[8];
    const float* bfc    = (const float*)d_in[9];
    const float* Wq     = (const float*)d_in[10];
    const float* bq     = (const float*)d_in[11];
    const float* Wk     = (const float*)d_in[12];
    const float* bk     = (const float*)d_in[13];
    const float* Wv     = (const float*)d_in[14];
    const float* bv     = (const float*)d_in[15];
    const float* Wo     = (const float*)d_in[16];
    const float* bo     = (const float*)d_in[17];
    const float* ln1g   = (const float*)d_in[18];
    const float* ln1b   = (const float*)d_in[19];
    const float* W1     = (const float*)d_in[20];
    const float* b1     = (const float*)d_in[21];
    const float* W2     = (const float*)d_in[22];
    const float* b2     = (const float*)d_in[23];
    const float* ln2g   = (const float*)d_in[24];
    const float* ln2b   = (const float*)d_in[25];
    const float* Wout   = (const float*)d_in[26];
    const float* bout   = (const float*)d_in[27];
    const int*   cls    = (const int*)d_in[28];

    float* base = nullptr;
    unsigned char* maskp = nullptr;
    __half *wt = nullptr, *af = nullptr, *bf = nullptr;
    cudaGetSymbolAddress((void**)&base,  g_scratch);
    cudaGetSymbolAddress((void**)&maskp, g_mask);
    cudaGetSymbolAddress((void**)&wt,    g_wt);
    cudaGetSymbolAddress((void**)&af,    g_a);
    cudaGetSymbolAddress((void**)&bf,    g_b);

    float* h  = base + 0ull * DSZ;
    float* t  = base + 6ull * DSZ;
    __half* qh = (__half*)(base + 1ull * DSZ);
    __half* kh = qh + DSZ;
    __half* vh = kh + DSZ;

    cudaFuncSetAttribute(gat_kernel,      cudaFuncAttributeMaxDynamicSharedMemorySize, GAT_SMEM_BYTES);
    cudaFuncSetAttribute(attn_kernel,     cudaFuncAttributeMaxDynamicSharedMemorySize, ATTN_SMEM_BYTES);
    cudaFuncSetAttribute(gemm_mma_kernel, cudaFuncAttributeMaxDynamicSharedMemorySize, GEMM_SMEM);
    cudaFuncSetAttribute(gemm_qkv_kernel, cudaFuncAttributeMaxDynamicSharedMemorySize, GEMM_SMEM);

    mask_kernel<<<NN, NN>>>(V_Adap, cls, maskp);
    gat_kernel<<<ROWS * 2, 256, GAT_SMEM_BYTES>>>(X, Wl, bl, Wr, br, att, gbias, Wfc, bfc,
                                                  maskp, h, af);

    // transpose all 12 weight matrices to fp16 in ONE launch
    {
        TsplitArgs ta;
        for (int l = 0; l < LAYERS; l++) {
            ta.w[l * 6 + 0] = Wq + (size_t)l * DSZ;
            ta.w[l * 6 + 1] = Wk + (size_t)l * DSZ;
            ta.w[l * 6 + 2] = Wv + (size_t)l * DSZ;
            ta.w[l * 6 + 3] = Wo + (size_t)l * DSZ;
            ta.w[l * 6 + 4] = W1 + (size_t)l * DSZ;
            ta.w[l * 6 + 5] = W2 + (size_t)l * DSZ;
        }
        dim3 tg(64, 64, 12);
        tsplit_all_kernel<<<tg, 256>>>(ta, wt);
    }

    dim3 gg(16, 16);
    dim3 gq(16, 16, 3);
    for (int l = 0; l < LAYERS; l++) {
        __half* w0  = wt + (size_t)(l * 6 + 0) * DSZ;
        __half* w1p = wt + (size_t)(l * 6 + 1) * DSZ;
        __half* w2p = wt + (size_t)(l * 6 + 2) * DSZ;
        __half* w3  = wt + (size_t)(l * 6 + 3) * DSZ;
        __half* w4  = wt + (size_t)(l * 6 + 4) * DSZ;
        __half* w5  = wt + (size_t)(l * 6 + 5) * DSZ;

        // fused QKV (one launch, 768 CTAs)
        QKVArgs qa;
        qa.A = af;
        qa.B0 = w0;  qa.B1 = w1p; qa.B2 = w2p;
        qa.bi0 = bq + l * DD; qa.bi1 = bk + l * DD; qa.bi2 = bv + l * DD;
        qa.O0 = qh;  qa.O1 = kh;  qa.O2 = vh;
        gemm_qkv_kernel<<<gq, GEMM_THREADS, GEMM_SMEM>>>(qa);

        attn_kernel<<<BB * NHEADS, 256, ATTN_SMEM_BYTES>>>(qh, kh, vh, af);
        gemm_mma_kernel<<<gg, GEMM_THREADS, GEMM_SMEM>>>(af, w3, bo + l * DD,
                                                h, t, nullptr, 2);
        ln_kernel<<<ROWS, 256>>>(t, h, ln1g + l * DD, ln1b + l * DD, af);
        gemm_mma_kernel<<<gg, GEMM_THREADS, GEMM_SMEM>>>(af, w4, b1 + l * DFF,
                                                nullptr, nullptr, bf, 3);
        gemm_mma_kernel<<<gg, GEMM_THREADS, GEMM_SMEM>>>(bf, w5, b2 + l * DD,
                                                h, t, nullptr, 2);
        ln_kernel<<<ROWS, 256>>>(t, h, ln2g + l * DD, ln2b + l * DD, af);
    }

    out_kernel<<<BB, 320>>>(h, Wout, bout, (float*)d_out);
}

// round 17
// speedup vs baseline: 1.0361x; 1.0059x over previous
#include <cuda_runtime.h>
#include <cuda_fp16.h>
#include <math.h>
#include <stdint.h>

// ---------------------------------------------------------------------------
// Shapes
// ---------------------------------------------------------------------------
#define BB     32
#define TT     64
#define NN     128
#define F_IN   16
#define SOUT   16
#define DD     2048
#define NHEADS 16
#define DH     128
#define DFF    2048
#define LAYERS 2
#define NOUT   10
#define ROWS   (BB*TT)
#define DSZ    (ROWS*DD)        // 4M elements; one 2048x2048 matrix

// ---------------------------------------------------------------------------
// Static scratch (allocation-free rule)
// ---------------------------------------------------------------------------
__device__ float g_scratch[7ull * DSZ];                 // h,(qkv fp16),-,-,-,tmp
__device__ unsigned char g_mask[NN * NN];
__device__ __half g_wt[12ull * DSZ];                    // transposed weights fp16
__device__ __half g_a[DSZ];                             // activation fp16 (A)
__device__ __half g_b[DSZ];                             // activation fp16 (B, FFN mid)

// ---------------------------------------------------------------------------
// Helpers
// ---------------------------------------------------------------------------
__device__ __forceinline__ uint32_t smem_u32(const void* p) {
    uint32_t a;
    asm("{ .reg .u64 t; cvta.to.shared.u64 t, %1; cvt.u32.u64 %0, t; }" : "=r"(a) : "l"(p));
    return a;
}

#define CP_ASYNC16(saddr, gptr) \
    asm volatile("cp.async.cg.shared.global [%0], [%1], 16;" :: "r"(saddr), "l"(gptr) : "memory")
#define CP_COMMIT()  asm volatile("cp.async.commit_group;" ::: "memory")
#define CP_WAIT0()   asm volatile("cp.async.wait_group 0;" ::: "memory")

__device__ __forceinline__ void ldsm_x4(uint32_t* r, uint32_t addr) {
    asm volatile("ldmatrix.sync.aligned.m8n8.x4.shared.b16 {%0,%1,%2,%3}, [%4];"
                 : "=r"(r[0]), "=r"(r[1]), "=r"(r[2]), "=r"(r[3]) : "r"(addr));
}
__device__ __forceinline__ void mma_fp16(float* d, const uint32_t* a, const uint32_t* b) {
    asm volatile(
        "mma.sync.aligned.m16n8k16.row.col.f32.f16.f16.f32 "
        "{%0,%1,%2,%3}, {%4,%5,%6,%7}, {%8,%9}, {%0,%1,%2,%3};"
        : "+f"(d[0]), "+f"(d[1]), "+f"(d[2]), "+f"(d[3])
        : "r"(a[0]), "r"(a[1]), "r"(a[2]), "r"(a[3]), "r"(b[0]), "r"(b[1]));
}

// ---------------------------------------------------------------------------
// Mask kernel
// ---------------------------------------------------------------------------
__global__ void mask_kernel(const float* __restrict__ V, const int* __restrict__ cls,
                            unsigned char* __restrict__ mask)
{
    int i = blockIdx.x, j = threadIdx.x;
    int c = *cls;
    float v = V[(size_t)c * NN * NN + i * NN + j];
    float a = (1.0f / (1.0f + expf(-v))) * (1.0f / (float)NN);
    mask[i * NN + j] = (a > 0.004f) || (i == j);
}

// ---------------------------------------------------------------------------
// GAT stage — j-split: 2 blocks per (b,t) row (unchanged from R16)
// ---------------------------------------------------------------------------
#define GAT_SMEM_FLOATS (2048+1024+1024+1024+64+64+64+64+16+8320+4160+8192)
#define GAT_SMEM_BYTES  (GAT_SMEM_FLOATS*4 + 128*64)

__global__ __launch_bounds__(256) void gat_kernel(
    const float* __restrict__ X,
    const float* __restrict__ Wl, const float* __restrict__ bl,
    const float* __restrict__ Wr, const float* __restrict__ br,
    const float* __restrict__ att, const float* __restrict__ gbias,
    const float* __restrict__ Wfc, const float* __restrict__ bfc,
    const unsigned char* __restrict__ gmask,
    float* __restrict__ H, __half* __restrict__ Hf)
{
    extern __shared__ float sm[];
    float* s_x   = sm;
    float* s_wl  = s_x   + 2048;
    float* s_wr  = s_wl  + 1024;
    float* s_wfc = s_wr  + 1024;
    float* s_att = s_wfc + 1024;
    float* s_bl  = s_att + 64;
    float* s_br  = s_bl  + 64;
    float* s_gb  = s_br  + 64;
    float* s_bfc = s_gb  + 64;
    float* s_xl  = s_bfc + 16;          // 128*65
    float* s_xr  = s_xl  + 8320;        // 64*65 ; reused as out
    float* s_e   = s_xr  + 4160;        // 128*64
    unsigned char* s_mask = (unsigned char*)(s_e + 8192);

    const int tid = threadIdx.x;
    const int r   = blockIdx.x >> 1;
    const int jh  = blockIdx.x & 1;
    const int j0  = jh * 64;
    const float* xg = X + (size_t)r * (NN * F_IN);

    for (int i = tid; i < 2048; i += 256) s_x[i] = xg[i];
    for (int i = tid; i < 1024; i += 256) { s_wl[i] = Wl[i]; s_wr[i] = Wr[i]; s_wfc[i] = Wfc[i]; }
    if (tid < 64) { s_att[tid] = att[tid]; s_bl[tid] = bl[tid]; s_br[tid] = br[tid]; s_gb[tid] = gbias[tid]; }
    if (tid < 16) s_bfc[tid] = bfc[tid];
    {
        uint32_t* sm32 = (uint32_t*)s_mask;
        const uint32_t* gm32 = (const uint32_t*)gmask;
        for (int idx = tid; idx < 2048; idx += 256) {
            int i = idx >> 4, w = idx & 15;
            sm32[i * 16 + w] = gm32[i * 32 + (j0 >> 2) + w];
        }
    }
    __syncthreads();

    for (int idx = tid; idx < 8192; idx += 256) {
        int i = idx >> 6, h = idx & 63;
        const float* xi = s_x + i * 16;
        float a = s_bl[h];
        #pragma unroll
        for (int f = 0; f < 16; f++) a += xi[f] * s_wl[f * 64 + h];
        s_xl[i * 65 + h] = a;
    }
    for (int idx = tid; idx < 4096; idx += 256) {
        int jl = idx >> 6, h = idx & 63;
        const float* xj = s_x + (j0 + jl) * 16;
        float b = s_br[h];
        #pragma unroll
        for (int f = 0; f < 16; f++) b += xj[f] * s_wr[f * 64 + h];
        s_xr[jl * 65 + h] = b;
    }
    __syncthreads();

    {
        const int ib = tid >> 4;
        const int jb = tid & 15;
        float acc[8][4];
        #pragma unroll
        for (int a = 0; a < 8; a++)
            #pragma unroll
            for (int b = 0; b < 4; b++) acc[a][b] = 0.f;

        for (int h = 0; h < 64; h++) {
            float av = s_att[h];
            float xls[8], xrs[4];
            #pragma unroll
            for (int u = 0; u < 8; u++) xls[u] = s_xl[(ib + u * 16) * 65 + h];
            #pragma unroll
            for (int w = 0; w < 4; w++) xrs[w] = s_xr[(jb + w * 16) * 65 + h];
            #pragma unroll
            for (int u = 0; u < 8; u++)
                #pragma unroll
                for (int w = 0; w < 4; w++) {
                    float v = xls[u] + xrs[w];
                    v = fmaxf(v, 0.2f * v);
                    acc[u][w] = fmaf(av, v, acc[u][w]);
                }
        }
        #pragma unroll
        for (int u = 0; u < 8; u++) {
            int i = ib + u * 16;
            #pragma unroll
            for (int w = 0; w < 4; w++) {
                int jl = jb + w * 16;
                s_e[i * 64 + jl] = s_mask[i * 64 + jl] ? acc[u][w] : -1e9f;
            }
        }
    }
    __syncthreads();

    {
        const int col  = tid >> 2;
        const int part = tid & 3;
        const int i0   = part * 32;
        float m = -1e30f;
        for (int i = i0; i < i0 + 32; i++) m = fmaxf(m, s_e[i * 64 + col]);
        m = fmaxf(m, __shfl_xor_sync(0xffffffffu, m, 1));
        m = fmaxf(m, __shfl_xor_sync(0xffffffffu, m, 2));
        float s = 0.f;
        for (int i = i0; i < i0 + 32; i++) {
            float ev = __expf(s_e[i * 64 + col] - m);
            s_e[i * 64 + col] = ev;
            s += ev;
        }
        s += __shfl_xor_sync(0xffffffffu, s, 1);
        s += __shfl_xor_sync(0xffffffffu, s, 2);
        float inv = 1.0f / s;
        for (int i = i0; i < i0 + 32; i++) s_e[i * 64 + col] *= inv;
    }
    __syncthreads();

    {
        const int jb = tid >> 4;
        const int hb = (tid & 15) * 4;
        float acc[4][4];
        #pragma unroll
        for (int a = 0; a < 4; a++)
            #pragma unroll
            for (int b = 0; b < 4; b++) acc[a][b] = 0.f;

        for (int i = 0; i < 128; i++) {
            float xv[4];
            #pragma unroll
            for (int u = 0; u < 4; u++) xv[u] = s_xl[i * 65 + hb + u];
            #pragma unroll
            for (int jj = 0; jj < 4; jj++) {
                float a = s_e[i * 64 + jb + jj * 16];
                #pragma unroll
                for (int u = 0; u < 4; u++)
                    acc[jj][u] = fmaf(a, xv[u], acc[jj][u]);
            }
        }
        #pragma unroll
        for (int jj = 0; jj < 4; jj++) {
            int jl = jb + jj * 16;
            #pragma unroll
            for (int u = 0; u < 4; u++)
                s_xr[jl * 65 + hb + u] = acc[jj][u] + s_gb[hb + u];
        }
    }
    __syncthreads();

    {
        const int jl = tid >> 2;
        const int s0 = (tid & 3) * 4;
        float acc[4];
        #pragma unroll
        for (int u = 0; u < 4; u++) acc[u] = s_bfc[s0 + u];
        const float* oj = s_xr + jl * 65;
        for (int h = 0; h < 64; h++) {
            float ov = oj[h];
            const float4 w = *(const float4*)&s_wfc[h * 16 + s0];
            acc[0] = fmaf(ov, w.x, acc[0]); acc[1] = fmaf(ov, w.y, acc[1]);
            acc[2] = fmaf(ov, w.z, acc[2]); acc[3] = fmaf(ov, w.w, acc[3]);
        }
        size_t base = (size_t)r * DD + (j0 + jl) * 16 + s0;
        #pragma unroll
        for (int u = 0; u < 4; u++) H[base + u] = acc[u];
        #pragma unroll
        for (int u = 0; u < 4; u++) Hf[base + u] = __float2half(acc[u]);
    }
}

// ---------------------------------------------------------------------------
// Weight transpose to fp16 — all 12 matrices, one launch; __half2 stores
// ---------------------------------------------------------------------------
struct TsplitArgs { const float* w[12]; };

__global__ __launch_bounds__(256) void tsplit_all_kernel(
    TsplitArgs args, __half* __restrict__ TBase)
{
    __shared__ float t[32][33];
    const int slot = blockIdx.z;
    const float* W = args.w[slot];
    __half* T = TBase + (size_t)slot * DSZ;

    const int bx = blockIdx.x, by = blockIdx.y;
    const int tx = threadIdx.x & 31, ty = threadIdx.x >> 5;
    #pragma unroll
    for (int i = 0; i < 4; i++) {
        int k = by * 32 + ty + i * 8;
        t[ty + i * 8][tx] = W[(size_t)k * 2048 + bx * 32 + tx];
    }
    __syncthreads();
    const int sx = threadIdx.x & 15;
    const int sy = threadIdx.x >> 4;
    #pragma unroll
    for (int i = 0; i < 2; i++) {
        int n  = bx * 32 + sy + i * 16;
        int k0 = by * 32 + sx * 2;
        __half2 hv;
        hv.x = __float2half(t[sx * 2][sy + i * 16]);
        hv.y = __float2half(t[sx * 2 + 1][sy + i * 16]);
        *(__half2*)(T + (size_t)n * 2048 + k0) = hv;
    }
}

// ---------------------------------------------------------------------------
// fp16 GEMM core (R14-proven: 512 threads, 16 warps, warp tile 32x32, BK=64)
// ---------------------------------------------------------------------------
#define GEMM_THREADS   512
#define GEMM_BK        64
#define GEMM_LDS       72
#define GEMM_ARR_BYTES (128*GEMM_LDS*2)
#define GEMM_STAGE     (2*GEMM_ARR_BYTES)
#define GEMM_SMEM      (2*GEMM_STAGE)

__device__ __forceinline__ void gemm_load_stage(
    const __half* A, const __half* B,
    uint32_t sbase, int buf, int m0, int n0, int kc, int tid)
{
    uint32_t sb = sbase + buf * GEMM_STAGE;
    const char* ga = (const char*)(A + (size_t)m0 * 2048 + kc);
    const char* gb = (const char*)(B + (size_t)n0 * 2048 + kc);
    #pragma unroll
    for (int j = 0; j < 2; j++) {
        int idx = tid + j * 512;
        int row = idx >> 3;
        int cu  = idx & 7;
        uint32_t soff = row * (GEMM_LDS * 2) + cu * 16;
        size_t  goff = (size_t)row * 4096 + cu * 16;
        CP_ASYNC16(sb + soff, ga + goff);
        CP_ASYNC16(sb + GEMM_ARR_BYTES + soff, gb + goff);
    }
}

__device__ __forceinline__ void gemm_body(
    const __half* A, const __half* B,
    const float* bias, const float* resid,
    float* C, __half* Of, int mode,
    int m0, int n0, char* dsm)
{
    const uint32_t sbase = smem_u32(dsm);
    const int tid  = threadIdx.x;
    const int wid  = tid >> 5;
    const int lane = tid & 31;
    const int wm   = wid & 3;
    const int wn   = wid >> 2;

    const int aoff = (wm * 32 + (lane & 15)) * GEMM_LDS + (lane >> 4) * 8;
    const int boff = (wn * 32 + (lane >> 4) * 8 + (lane & 7)) * GEMM_LDS + ((lane >> 3) & 1) * 8;

    float acc[2][4][4];
    #pragma unroll
    for (int mt = 0; mt < 2; mt++)
        #pragma unroll
        for (int nt = 0; nt < 4; nt++)
            #pragma unroll
            for (int c = 0; c < 4; c++) acc[mt][nt][c] = 0.f;

    gemm_load_stage(A, B, sbase, 0, m0, n0, 0, tid);
    CP_COMMIT();
    CP_WAIT0();
    __syncthreads();

    const int NCHUNK = 2048 / GEMM_BK;
    for (int i = 0; i < NCHUNK; i++) {
        const int buf = i & 1;
        if (i + 1 < NCHUNK) {
            gemm_load_stage(A, B, sbase, buf ^ 1, m0, n0, (i + 1) * GEMM_BK, tid);
            CP_COMMIT();
        }

        const uint32_t aB = sbase + buf * GEMM_STAGE;
        const uint32_t bB = aB + GEMM_ARR_BYTES;

        #pragma unroll
        for (int kt = 0; kt < 4; kt++) {
            uint32_t af[2][4];
            #pragma unroll
            for (int mt = 0; mt < 2; mt++) {
                uint32_t ao = (aoff + mt * 16 * GEMM_LDS + kt * 16) * 2;
                ldsm_x4(af[mt], aB + ao);
            }
            #pragma unroll
            for (int np = 0; np < 2; np++) {
                uint32_t bo = (boff + np * 16 * GEMM_LDS + kt * 16) * 2;
                uint32_t bf[4];
                ldsm_x4(bf, bB + bo);
                #pragma unroll
                for (int half = 0; half < 2; half++) {
                    int nt = np * 2 + half;
                    #pragma unroll
                    for (int mt = 0; mt < 2; mt++)
                        mma_fp16(acc[mt][nt], af[mt], bf + half * 2);
                }
            }
        }

        CP_WAIT0();
        __syncthreads();
    }

    const int g  = lane >> 2;
    const int t2 = lane & 3;
    #pragma unroll
    for (int mt = 0; mt < 2; mt++) {
        #pragma unroll
        for (int nt = 0; nt < 4; nt++) {
            int row = m0 + wm * 32 + mt * 16 + g;
            int col = n0 + wn * 32 + nt * 8 + t2 * 2;
            float b0 = __ldg(bias + col), b1 = __ldg(bias + col + 1);
            #pragma unroll
            for (int half = 0; half < 2; half++) {
                int rr = row + half * 8;
                float v0 = acc[mt][nt][half * 2 + 0] + b0;
                float v1 = acc[mt][nt][half * 2 + 1] + b1;
                size_t off = (size_t)rr * 2048 + col;
                if (mode >= 3) {
                    if (mode == 3) { v0 = fmaxf(v0, 0.f); v1 = fmaxf(v1, 0.f); }
                    __half2 hp; hp.x = __float2half(v0); hp.y = __float2half(v1);
                    *(uint32_t*)(Of + off) = *(uint32_t*)&hp;
                } else {
                    if (mode == 2) {
                        const float2 rp = *(const float2*)(resid + off);
                        v0 += rp.x; v1 += rp.y;
                    }
                    float2 o; o.x = v0; o.y = v1;
                    *(float2*)(C + off) = o;
                }
            }
        }
    }
}

__global__ __launch_bounds__(GEMM_THREADS, 1)
void gemm_mma_kernel(
    const __half* __restrict__ A, const __half* __restrict__ B,
    const float* __restrict__ bias, const float* __restrict__ resid,
    float* __restrict__ C, __half* __restrict__ Of, int mode)
{
    extern __shared__ char dsm[];
    gemm_body(A, B, bias, resid, C, Of, mode,
              blockIdx.y * 128, blockIdx.x * 128, dsm);
}

struct QKVArgs {
    const __half* A;
    const __half* B0; const __half* B1; const __half* B2;
    const float* bi0; const float* bi1; const float* bi2;
    __half* O0; __half* O1; __half* O2;
};

__global__ __launch_bounds__(GEMM_THREADS, 1)
void gemm_qkv_kernel(QKVArgs a)
{
    extern __shared__ char dsm[];
    const int z = blockIdx.z;
    const __half* B = (z == 0) ? a.B0 : (z == 1) ? a.B1 : a.B2;
    const float* bi = (z == 0) ? a.bi0 : (z == 1) ? a.bi1 : a.bi2;
    __half* O       = (z == 0) ? a.O0 : (z == 1) ? a.O1 : a.O2;
    gemm_body(a.A, B, bi, nullptr, nullptr, O, 4,
              blockIdx.y * 128, blockIdx.x * 128, dsm);
}

// ---------------------------------------------------------------------------
// Attention — fp16 smem (stride 130), 3 blocks/SM, vectorized I/O
// ---------------------------------------------------------------------------
#define ATTN_STR   130
#define ATTN_SMEM_BYTES (3*64*ATTN_STR*2 + 64*65*4)   // 66560

__global__ __launch_bounds__(256) void attn_kernel(
    const __half* __restrict__ Qf, const __half* __restrict__ Kf,
    const __half* __restrict__ Vf, __half* __restrict__ AOf)
{
    extern __shared__ char smc[];
    __half* sq = (__half*)smc;              // 64*130
    __half* sk = sq + 64 * ATTN_STR;        // 64*130
    __half* sv = sk + 64 * ATTN_STR;        // 64*130
    float*  sc = (float*)(sv + 64 * ATTN_STR);  // 64*65

    const int tid = threadIdx.x;
    const int b   = blockIdx.x >> 4;
    const int hd  = blockIdx.x & 15;
    const size_t base = (size_t)(b * TT) * DD + hd * DH;
    const float SCALE = 0.08838834764831845f;   // 1/sqrt(128)

    // vectorized load: 8 halves per thread per iter
    #pragma unroll
    for (int it = 0; it < 4; it++) {
        int idx = tid + it * 256;           // 0..1023 uint4 chunks
        int t   = idx >> 4;
        int d8  = (idx & 15) * 8;
        size_t g = base + (size_t)t * DD + d8;
        uint4 q4 = *(const uint4*)(Qf + g);
        uint4 k4 = *(const uint4*)(Kf + g);
        uint4 v4 = *(const uint4*)(Vf + g);
        uint32_t* qs = (uint32_t*)(sq + t * ATTN_STR + d8);
        uint32_t* ks = (uint32_t*)(sk + t * ATTN_STR + d8);
        uint32_t* vs = (uint32_t*)(sv + t * ATTN_STR + d8);
        qs[0] = q4.x; qs[1] = q4.y; qs[2] = q4.z; qs[3] = q4.w;
        ks[0] = k4.x; ks[1] = k4.y; ks[2] = k4.z; ks[3] = k4.w;
        vs[0] = v4.x; vs[1] = v4.y; vs[2] = v4.z; vs[3] = v4.w;
    }
    __syncthreads();

    // scores: 4x4 per thread, half2 loads
    {
        const int a    = tid >> 4;
        const int bcol = tid & 15;
        float acc[4][4];
        #pragma unroll
        for (int u = 0; u < 4; u++)
            #pragma unroll
            for (int w = 0; w < 4; w++) acc[u][w] = 0.f;

        for (int p = 0; p < 64; p++) {
            float2 qv[4], kv[4];
            #pragma unroll
            for (int u = 0; u < 4; u++)
                qv[u] = __half22float2(*(__half2*)(sq + (a + u * 16) * ATTN_STR + p * 2));
            #pragma unroll
            for (int w = 0; w < 4; w++)
                kv[w] = __half22float2(*(__half2*)(sk + (bcol + w * 16) * ATTN_STR + p * 2));
            #pragma unroll
            for (int u = 0; u < 4; u++)
                #pragma unroll
                for (int w = 0; w < 4; w++) {
                    acc[u][w] = fmaf(qv[u].x, kv[w].x, acc[u][w]);
                    acc[u][w] = fmaf(qv[u].y, kv[w].y, acc[u][w]);
                }
        }
        #pragma unroll
        for (int u = 0; u < 4; u++)
            #pragma unroll
            for (int w = 0; w < 4; w++)
                sc[(a + u * 16) * 65 + bcol + w * 16] = acc[u][w] * SCALE;
    }
    __syncthreads();

    // row softmax: 4 threads per row
    {
        const int row  = tid >> 2;
        const int part = tid & 3;
        float* rp = sc + row * 65 + part * 16;
        float m = -1e30f;
        #pragma unroll
        for (int i = 0; i < 16; i++) m = fmaxf(m, rp[i]);
        m = fmaxf(m, __shfl_xor_sync(0xffffffffu, m, 1));
        m = fmaxf(m, __shfl_xor_sync(0xffffffffu, m, 2));
        float s = 0.f;
        #pragma unroll
        for (int i = 0; i < 16; i++) { float e = __expf(rp[i] - m); rp[i] = e; s += e; }
        s += __shfl_xor_sync(0xffffffffu, s, 1);
        s += __shfl_xor_sync(0xffffffffu, s, 2);
        float inv = 1.0f / s;
        #pragma unroll
        for (int i = 0; i < 16; i++) rp[i] *= inv;
    }
    __syncthreads();

    // ao: 8 t x 2 d-pairs per thread; half2 V loads, half2 output stores
    {
        const int tg = tid >> 5;
        const int dg = tid & 31;
        float2 acc[8][2];
        #pragma unroll
        for (int u = 0; u < 8; u++)
            #pragma unroll
            for (int dd = 0; dd < 2; dd++) { acc[u][dd].x = 0.f; acc[u][dd].y = 0.f; }

        for (int t2 = 0; t2 < 64; t2++) {
            float av[8];
            float2 vv[2];
            #pragma unroll
            for (int u = 0; u < 8; u++) av[u] = sc[(tg * 8 + u) * 65 + t2];
            #pragma unroll
            for (int dd = 0; dd < 2; dd++)
                vv[dd] = __half22float2(*(__half2*)(sv + t2 * ATTN_STR + (dg + dd * 32) * 2));
            #pragma unroll
            for (int u = 0; u < 8; u++)
                #pragma unroll
                for (int dd = 0; dd < 2; dd++) {
                    acc[u][dd].x = fmaf(av[u], vv[dd].x, acc[u][dd].x);
                    acc[u][dd].y = fmaf(av[u], vv[dd].y, acc[u][dd].y);
                }
        }
        #pragma unroll
        for (int u = 0; u < 8; u++) {
            int t = tg * 8 + u;
            #pragma unroll
            for (int dd = 0; dd < 2; dd++) {
                __half2 hp;
                hp.x = __float2half(acc[u][dd].x);
                hp.y = __float2half(acc[u][dd].y);
                *(__half2*)(AOf + base + (size_t)t * DD + (dg + dd * 32) * 2) = hp;
            }
        }
    }
}

// ---------------------------------------------------------------------------
// LayerNorm: fp32 out + fp16 out
// ---------------------------------------------------------------------------
__global__ __launch_bounds__(256) void ln_kernel(
    const float* __restrict__ x, float* __restrict__ y,
    const float* __restrict__ g, const float* __restrict__ b,
    __half* __restrict__ Yf)
{
    __shared__ float red[256];
    const int row = blockIdx.x, tid = threadIdx.x;
    const float* xr = x + (size_t)row * DD;

    float s = 0.f;
    for (int i = tid; i < DD; i += 256) s += xr[i];
    red[tid] = s; __syncthreads();
    for (int st = 128; st > 0; st >>= 1) { if (tid < st) red[tid] += red[tid + st]; __syncthreads(); }
    float mu = red[0] * (1.0f / DD);
    __syncthreads();

    float v = 0.f;
    for (int i = tid; i < DD; i += 256) { float d = xr[i] - mu; v += d * d; }
    red[tid] = v; __syncthreads();
    for (int st = 128; st > 0; st >>= 1) { if (tid < st) red[tid] += red[tid + st]; __syncthreads(); }
    float var = red[0] * (1.0f / DD);
    float inv = 1.0f / sqrtf(var + 1e-5f);

    float* yr = y + (size_t)row * DD;
    __half* fr = Yf + (size_t)row * DD;
    for (int i = tid; i < DD; i += 256) {
        float val = (xr[i] - mu) * inv * g[i] + b[i];
        yr[i] = val;
        fr[i] = __float2half(val);
    }
}

// ---------------------------------------------------------------------------
// Final projection
// ---------------------------------------------------------------------------
__global__ void out_kernel(const float* __restrict__ H, const float* __restrict__ Wout,
                           const float* __restrict__ bout, float* __restrict__ out)
{
    int b = blockIdx.x;
    int o = threadIdx.x >> 5;
    int lane = threadIdx.x & 31;
    if (o >= NOUT) return;
    const float* h = H + (size_t)(b * TT + TT - 1) * DD;
    float acc = 0.f;
    for (int i = lane; i < DD; i += 32)
        acc += h[i] * Wout[i * NOUT + o];
    #pragma unroll
    for (int s = 16; s > 0; s >>= 1)
        acc += __shfl_down_sync(0xffffffffu, acc, s);
    if (lane == 0) out[b * NOUT + o] = acc + bout[o];
}

// ---------------------------------------------------------------------------
// Launch
// ---------------------------------------------------------------------------
extern "C" void kernel_launch(void* const* d_in, const int* in_sizes, int n_in,
                              void* d_out, int out_size)
{
    (void)in_sizes; (void)n_in; (void)out_size;

    const float* X      = (const float*)d_in[0];
    const float* V_Adap = (const float*)d_in[1];
    const float* Wl     = (const float*)d_in[2];
    const float* bl     = (const float*)d_in[3];
    const float* Wr     = (const float*)d_in[4];
    const float* br     = (const float*)d_in[5];
    const float* att    = (const float*)d_in[6];
    const float* gbias  = (const float*)d_in[7];
    const float* Wfc    = (const float*)d_in[8];
    const float* bfc    = (const float*)d_in[9];
    const float* Wq     = (const float*)d_in[10];
    const float* bq     = (const float*)d_in[11];
    const float* Wk     = (const float*)d_in[12];
    const float* bk     = (const float*)d_in[13];
    const float* Wv     = (const float*)d_in[14];
    const float* bv     = (const float*)d_in[15];
    const float* Wo     = (const float*)d_in[16];
    const float* bo     = (const float*)d_in[17];
    const float* ln1g   = (const float*)d_in[18];
    const float* ln1b   = (const float*)d_in[19];
    const float* W1     = (const float*)d_in[20];
    const float* b1     = (const float*)d_in[21];
    const float* W2     = (const float*)d_in[22];
    const float* b2     = (const float*)d_in[23];
    const float* ln2g   = (const float*)d_in[24];
    const float* ln2b   = (const float*)d_in[25];
    const float* Wout   = (const float*)d_in[26];
    const float* bout   = (const float*)d_in[27];
    const int*   cls    = (const int*)d_in[28];

    float* base = nullptr;
    unsigned char* maskp = nullptr;
    __half *wt = nullptr, *af = nullptr, *bf = nullptr;
    cudaGetSymbolAddress((void**)&base,  g_scratch);
    cudaGetSymbolAddress((void**)&maskp, g_mask);
    cudaGetSymbolAddress((void**)&wt,    g_wt);
    cudaGetSymbolAddress((void**)&af,    g_a);
    cudaGetSymbolAddress((void**)&bf,    g_b);

    float* h  = base + 0ull * DSZ;
    float* t  = base + 6ull * DSZ;
    __half* qh = (__half*)(base + 1ull * DSZ);
    __half* kh = qh + DSZ;
    __half* vh = kh + DSZ;

    cudaFuncSetAttribute(gat_kernel,      cudaFuncAttributeMaxDynamicSharedMemorySize, GAT_SMEM_BYTES);
    cudaFuncSetAttribute(attn_kernel,     cudaFuncAttributeMaxDynamicSharedMemorySize, ATTN_SMEM_BYTES);
    cudaFuncSetAttribute(gemm_mma_kernel, cudaFuncAttributeMaxDynamicSharedMemorySize, GEMM_SMEM);
    cudaFuncSetAttribute(gemm_qkv_kernel, cudaFuncAttributeMaxDynamicSharedMemorySize, GEMM_SMEM);

    mask_kernel<<<NN, NN>>>(V_Adap, cls, maskp);
    gat_kernel<<<ROWS * 2, 256, GAT_SMEM_BYTES>>>(X, Wl, bl, Wr, br, att, gbias, Wfc, bfc,
                                                  maskp, h, af);

    {
        TsplitArgs ta;
        for (int l = 0; l < LAYERS; l++) {
            ta.w[l * 6 + 0] = Wq + (size_t)l * DSZ;
            ta.w[l * 6 + 1] = Wk + (size_t)l * DSZ;
            ta.w[l * 6 + 2] = Wv + (size_t)l * DSZ;
            ta.w[l * 6 + 3] = Wo + (size_t)l * DSZ;
            ta.w[l * 6 + 4] = W1 + (size_t)l * DSZ;
            ta.w[l * 6 + 5] = W2 + (size_t)l * DSZ;
        }
        dim3 tg(64, 64, 12);
        tsplit_all_kernel<<<tg, 256>>>(ta, wt);
    }

    dim3 gg(16, 16);
    dim3 gq(16, 16, 3);
    for (int l = 0; l < LAYERS; l++) {
        __half* w0  = wt + (size_t)(l * 6 + 0) * DSZ;
        __half* w1p = wt + (size_t)(l * 6 + 1) * DSZ;
        __half* w2p = wt + (size_t)(l * 6 + 2) * DSZ;
        __half* w3  = wt + (size_t)(l * 6 + 3) * DSZ;
        __half* w4  = wt + (size_t)(l * 6 + 4) * DSZ;
        __half* w5  = wt + (size_t)(l * 6 + 5) * DSZ;

        QKVArgs qa;
        qa.A = af;
        qa.B0 = w0;  qa.B1 = w1p; qa.B2 = w2p;
        qa.bi0 = bq + l * DD; qa.bi1 = bk + l * DD; qa.bi2 = bv + l * DD;
        qa.O0 = qh;  qa.O1 = kh;  qa.O2 = vh;
        gemm_qkv_kernel<<<gq, GEMM_THREADS, GEMM_SMEM>>>(qa);

        attn_kernel<<<BB * NHEADS, 256, ATTN_SMEM_BYTES>>>(qh, kh, vh, af);
        gemm_mma_kernel<<<gg, GEMM_THREADS, GEMM_SMEM>>>(af, w3, bo + l * DD,
                                                h, t, nullptr, 2);
        ln_kernel<<<ROWS, 256>>>(t, h, ln1g + l * DD, ln1b + l * DD, af);
        gemm_mma_kernel<<<gg, GEMM_THREADS, GEMM_SMEM>>>(af, w4, b1 + l * DFF,
                                                nullptr, nullptr, bf, 3);
        gemm_mma_kernel<<<gg, GEMM_THREADS, GEMM_SMEM>>>(bf, w5, b2 + l * DD,
                                                h, t, nullptr, 2);
        ln_kernel<<<ROWS, 256>>>(t, h, ln2g + l * DD, ln2b + l * DD, af);
    }

    out_kernel<<<BB, 320>>>(h, Wout, bout, (float*)d_out);
}